// round 17
// baseline (speedup 1.0000x reference)
#include <cuda_runtime.h>
#include <cuda_bf16.h>
#include <math.h>
#include <cstdint>

// Problem constants
#define NN   16384
#define HID  128
#define PROP 64
#define SPACE 4
#define KNB  40
#define NLAYERS 4
#define FULLMASK 0xFFFFFFFFu

// Scratch (static device allocations; no cudaMalloc allowed)
__device__ float g_x[NN * HID];
__device__ float g_y[NN * HID];
__device__ float g_s[NN * SPACE];
__device__ float g_h[NN * PROP];
__device__ float g_agg[NN * HID];
__device__ float g_w[NN * KNB];
__device__ int   g_idx[NN * KNB];

// ids: 0=g_x, 1=g_y, 2=g_agg, 3=g_h, 4=g_s, -1=arg.
__device__ __forceinline__ const float* resolve_c(const float* p, int id) {
    switch (id) {
        case 0: return g_x;
        case 1: return g_y;
        case 2: return g_agg;
        case 3: return g_h;
        case 4: return g_s;
        default: return p;
    }
}
__device__ __forceinline__ float* resolve_w(float* p, int id) {
    switch (id) {
        case 0: return g_x;
        case 1: return g_y;
        case 2: return g_agg;
        case 3: return g_h;
        case 4: return g_s;
        default: return p;
    }
}

// Monotone float <-> uint key maps (for redux.max over distances).
__device__ __forceinline__ unsigned fkey(float f) {
    unsigned u = __float_as_uint(f);
    return u ^ ((unsigned)((int)u >> 31) | 0x80000000u);
}
__device__ __forceinline__ float unfkey(unsigned k) {
    unsigned m = (k & 0x80000000u) ? 0x80000000u : 0xFFFFFFFFu;
    return __uint_as_float(k ^ m);
}

__device__ __forceinline__ unsigned packbf(__nv_bfloat16 a, __nv_bfloat16 b) {
    return (unsigned)__bfloat16_as_ushort(a) | ((unsigned)__bfloat16_as_ushort(b) << 16);
}
__device__ __forceinline__ void bfsplit(float f, __nv_bfloat16& h, __nv_bfloat16& l) {
    h = __float2bfloat16_rn(f);
    l = __float2bfloat16_rn(f - __bfloat162float(h));
}

__device__ __forceinline__ void mma16816(float* c, const uint32_t* a,
                                         uint32_t b0, uint32_t b1) {
    asm volatile(
        "mma.sync.aligned.m16n8k16.row.col.f32.bf16.bf16.f32 "
        "{%0,%1,%2,%3}, {%4,%5,%6,%7}, {%8,%9}, {%0,%1,%2,%3};"
        : "+f"(c[0]), "+f"(c[1]), "+f"(c[2]), "+f"(c[3])
        : "r"(a[0]), "r"(a[1]), "r"(a[2]), "r"(a[3]), "r"(b0), "r"(b1));
}

// ===========================================================================
// Tensor-core GEMM v2 via mma.sync: C[N x MD] = act(A[N x KD] @ W[KD x MD] + b)
// Grid = 256 CTAs x 128 threads (64 rows per CTA, 4 warps x 16-row stripes).
// A fragments loaded DIRECTLY from GMEM (float2 per fragment reg) and split
// to bf16 hi/lo in registers. W staged per (nhalf, khalf-of-128) phase into
// stride-68 padded smem (conflict-free B-fragment LDS). 3 mma products:
// AhBh + AhBl + AlBh (AlBl ~2^-16, dropped).
// ===========================================================================
template <int KD, int MD, bool RELU, bool TWOSRC>
__global__ void __launch_bounds__(128) mmagemm_k(const float* __restrict__ Ap, int aid,
                                                 const float* __restrict__ W,
                                                 const float* __restrict__ B,
                                                 float* __restrict__ Cp, int cid) {
    constexpr int NH = MD / 64;   // N halves
    constexpr int KH = KD / 128;  // K chunks of 128
    const float* __restrict__ A = resolve_c(Ap, aid);
    float* __restrict__ C = resolve_w(Cp, cid);

    // W tile: 64 n-cols x 64 k-pairs, stride 68 words -> conflict-free frag LDS
    __shared__ uint32_t sBh[64][68], sBl[64][68];
    __shared__ float sBias[MD];

    const int t = threadIdx.x;
    const int warp = t >> 5;
    const int lane = t & 31;
    const int g = lane >> 2;      // fragment row group
    const int t4 = lane & 3;      // thread-in-group
    const int row0 = blockIdx.x * 64;

    if (t < MD) sBias[t] = B[t];

    const int r0 = row0 + warp * 16 + g;
    const int r1 = r0 + 8;

#pragma unroll
    for (int nh = 0; nh < NH; ++nh) {
        float acc[8][4];
#pragma unroll
        for (int nc = 0; nc < 8; ++nc)
#pragma unroll
            for (int q = 0; q < 4; ++q) acc[nc][q] = 0.f;

#pragma unroll
        for (int kh = 0; kh < KH; ++kh) {
            __syncthreads();  // previous phase fragment reads complete
            // stage W[kh*128 .. +128][nh*64 .. +64] as hi/lo packed k-pairs
            for (int e = t; e < 64 * 64; e += 128) {
                const int n = e & 63;
                const int kp = e >> 6;   // k-pair 0..63
                float f0 = W[(kh * 128 + 2 * kp) * MD + nh * 64 + n];
                float f1 = W[(kh * 128 + 2 * kp + 1) * MD + nh * 64 + n];
                __nv_bfloat16 h0, l0, h1, l1;
                bfsplit(f0, h0, l0);
                bfsplit(f1, h1, l1);
                sBh[n][kp] = packbf(h0, h1);
                sBl[n][kp] = packbf(l0, l1);
            }
            __syncthreads();

#pragma unroll
            for (int kc = 0; kc < 8; ++kc) {
                const int kA = kh * 128 + kc * 16 + 2 * t4;  // frag k base
                float2 f00, f10, f01, f11;
                if (TWOSRC) {
                    if (kh == 0) {
                        f00 = *reinterpret_cast<const float2*>(&g_y[r0 * 128 + kA]);
                        f10 = *reinterpret_cast<const float2*>(&g_y[r1 * 128 + kA]);
                        f01 = *reinterpret_cast<const float2*>(&g_y[r0 * 128 + kA + 8]);
                        f11 = *reinterpret_cast<const float2*>(&g_y[r1 * 128 + kA + 8]);
                    } else {
                        const int ka = kA - 128;
                        f00 = *reinterpret_cast<const float2*>(&g_agg[r0 * 128 + ka]);
                        f10 = *reinterpret_cast<const float2*>(&g_agg[r1 * 128 + ka]);
                        f01 = *reinterpret_cast<const float2*>(&g_agg[r0 * 128 + ka + 8]);
                        f11 = *reinterpret_cast<const float2*>(&g_agg[r1 * 128 + ka + 8]);
                    }
                } else {
                    f00 = *reinterpret_cast<const float2*>(&A[r0 * KD + kA]);
                    f10 = *reinterpret_cast<const float2*>(&A[r1 * KD + kA]);
                    f01 = *reinterpret_cast<const float2*>(&A[r0 * KD + kA + 8]);
                    f11 = *reinterpret_cast<const float2*>(&A[r1 * KD + kA + 8]);
                }
                uint32_t ah[4], al[4];
                {
                    __nv_bfloat16 h0, l0, h1, l1;
                    bfsplit(f00.x, h0, l0); bfsplit(f00.y, h1, l1);
                    ah[0] = packbf(h0, h1); al[0] = packbf(l0, l1);
                    bfsplit(f10.x, h0, l0); bfsplit(f10.y, h1, l1);
                    ah[1] = packbf(h0, h1); al[1] = packbf(l0, l1);
                    bfsplit(f01.x, h0, l0); bfsplit(f01.y, h1, l1);
                    ah[2] = packbf(h0, h1); al[2] = packbf(l0, l1);
                    bfsplit(f11.x, h0, l0); bfsplit(f11.y, h1, l1);
                    ah[3] = packbf(h0, h1); al[3] = packbf(l0, l1);
                }
#pragma unroll
                for (int nc = 0; nc < 8; ++nc) {
                    const int bn = nc * 8 + g;
                    const int kp0 = kc * 8 + t4;
                    uint32_t bh0 = sBh[bn][kp0], bh1 = sBh[bn][kp0 + 4];
                    uint32_t bl0 = sBl[bn][kp0], bl1 = sBl[bn][kp0 + 4];
                    mma16816(acc[nc], ah, bh0, bh1);
                    mma16816(acc[nc], ah, bl0, bl1);
                    mma16816(acc[nc], al, bh0, bh1);
                }
            }
        }

        // epilogue for this N-half (registers + read-only sBias only)
#pragma unroll
        for (int nc = 0; nc < 8; ++nc) {
            const int c0 = nh * 64 + nc * 8 + 2 * t4;
            float b0 = sBias[c0], b1 = sBias[c0 + 1];
            float2 o0, o1;
            o0.x = acc[nc][0] + b0; o0.y = acc[nc][1] + b1;
            o1.x = acc[nc][2] + b0; o1.y = acc[nc][3] + b1;
            if (RELU) {
                o0.x = fmaxf(o0.x, 0.f); o0.y = fmaxf(o0.y, 0.f);
                o1.x = fmaxf(o1.x, 0.f); o1.y = fmaxf(o1.y, 0.f);
            }
            *reinterpret_cast<float2*>(&C[r0 * MD + c0]) = o0;
            *reinterpret_cast<float2*>(&C[r1 * MD + c0]) = o1;
        }
    }
}

// ---------------------------------------------------------------------------
// SIMT SGEMM kept only for fc1 (KD=9).
// ---------------------------------------------------------------------------
template <int KD, int MD, bool RELU>
__global__ void __launch_bounds__(256) gemm_k(const float* __restrict__ Ap, int aid,
                                              const float* __restrict__ W,
                                              const float* __restrict__ B,
                                              float* __restrict__ Cp, int cid) {
    constexpr int RPT = MD / 8;
    const float* __restrict__ A = resolve_c(Ap, aid);
    float* __restrict__ C = resolve_w(Cp, cid);

    __shared__ float As[32 * KD];
    const int t = threadIdx.x;
    const int c = t % MD;
    const int h = t / MD;
    const int row0 = blockIdx.x * 32;

    for (int i = t; i < 32 * KD; i += 256) As[i] = A[row0 * KD + i];
    __syncthreads();

    float acc[RPT];
#pragma unroll
    for (int r = 0; r < RPT; ++r) acc[r] = 0.f;

    const float* Asb = As + (h * RPT) * KD;
    for (int k = 0; k < KD; ++k) {
        float wv = W[k * MD + c];
#pragma unroll
        for (int r = 0; r < RPT; ++r) acc[r] = fmaf(Asb[r * KD + k], wv, acc[r]);
    }

    float bb = B[c];
#pragma unroll
    for (int r = 0; r < RPT; ++r) {
        float v = acc[r] + bb;
        if (RELU) v = fmaxf(v, 0.f);
        C[(row0 + h * RPT + r) * MD + c] = v;
    }
}

// ---------------------------------------------------------------------------
// Small GEMM: C[N x 4] = act(A[N x 128] @ W[128 x 4] + b).
// ---------------------------------------------------------------------------
template <bool RELU>
__global__ void __launch_bounds__(128) gemm4_k(const float* __restrict__ Ap, int aid,
                                               const float* __restrict__ W,
                                               const float* __restrict__ B,
                                               float* __restrict__ Cp, int cid) {
    const float* __restrict__ A = resolve_c(Ap, aid);
    float* __restrict__ C = resolve_w(Cp, cid);

    __shared__ float As[32][132];
    const int t = threadIdx.x;
    const int row0 = blockIdx.x * 32;

    for (int i = t; i < 32 * 128; i += 128) As[i >> 7][i & 127] = A[row0 * 128 + i];
    __syncthreads();

    const int r = t >> 2, c = t & 3;
    float acc = 0.f;
#pragma unroll 8
    for (int k = 0; k < 128; ++k) acc = fmaf(As[r][k], W[k * 4 + c], acc);

    float v = acc + B[c];
    if (RELU) v = fmaxf(v, 0.f);
    C[(row0 + r) * 4 + c] = v;
}

// ---------------------------------------------------------------------------
// kNN v6: 4 rows per warp. Each vj/s2j LDS is amortized over 4 query rows
// held in registers; common case is ONE combined ballot per 32-j step.
// Per-row insert path = R11 known-good (cached argmax key + single redux).
// Threshold shrinks monotonically, so per-row re-filtering stays exact.
// ---------------------------------------------------------------------------
__global__ void __launch_bounds__(256) knn_k() {
    const float* __restrict__ S = g_s;
    int* __restrict__ IDX = g_idx;
    float* __restrict__ WW = g_w;

    constexpr int TJ = 512;
    __shared__ float4 sj[TJ];
    __shared__ float  s2j[TJ];

    const int t = threadIdx.x;
    const int lane = t & 31;
    const int wrp = t >> 5;                       // 8 warps/block
    const int row4 = (blockIdx.x * 8 + wrp) * 4;  // 4 rows per warp

    const float INFP = __int_as_float(0x7f800000);
    const float INFN = __int_as_float(0xff800000);

    float4 si[4];
    float s2i[4];
    float bd0[4], bd1[4], worstAdj[4];
    int bi0[4], bi1[4];
    unsigned mymk[4], bmaxKey[4];
#pragma unroll
    for (int q = 0; q < 4; ++q) {
        si[q] = reinterpret_cast<const float4*>(S)[row4 + q];
        float s2 = si[q].x * si[q].x;
        s2 = fmaf(si[q].y, si[q].y, s2);
        s2 = fmaf(si[q].z, si[q].z, s2);
        s2 = fmaf(si[q].w, si[q].w, s2);
        s2i[q] = s2;
        bd0[q] = INFP;
        bd1[q] = (lane < 8) ? INFP : INFN;
        bi0[q] = 0; bi1[q] = 0;
        mymk[q] = fkey(INFP);
        bmaxKey[q] = mymk[q];
        worstAdj[q] = INFP;
    }

    for (int base = 0; base < NN; base += TJ) {
        __syncthreads();
        for (int i = t; i < TJ; i += 256) {
            float4 v = reinterpret_cast<const float4*>(S)[base + i];
            float s2 = v.x * v.x;
            s2 = fmaf(v.y, v.y, s2);
            s2 = fmaf(v.z, v.z, s2);
            s2 = fmaf(v.w, v.w, s2);
            sj[i] = v;
            s2j[i] = s2;
        }
        __syncthreads();

        for (int stp = 0; stp < TJ; stp += 32) {
            const float4 vj = sj[stp + lane];
            const float s2v = s2j[stp + lane];
            float tv[4];
            bool any = false;
#pragma unroll
            for (int q = 0; q < 4; ++q) {
                float dot = si[q].x * vj.x;
                dot = fmaf(si[q].y, vj.y, dot);
                dot = fmaf(si[q].z, vj.z, dot);
                dot = fmaf(si[q].w, vj.w, dot);
                tv[q] = fmaf(-2.f, dot, s2v);
                any |= (tv[q] < worstAdj[q]);
            }
            if (!__ballot_sync(FULLMASK, any)) continue;

#pragma unroll
            for (int q = 0; q < 4; ++q) {
                unsigned mask = __ballot_sync(FULLMASK, tv[q] < worstAdj[q]);
                while (mask) {
                    int src = __ffs(mask) - 1;
                    mask &= mask - 1;
                    float tc = __shfl_sync(FULLMASK, tv[q], src);
                    if (tc < worstAdj[q]) {
                        float dc = tc + s2i[q];
                        int jc = base + stp + src;
                        unsigned sel = __ballot_sync(FULLMASK, mymk[q] == bmaxKey[q]);
                        if (lane == __ffs(sel) - 1) {
                            if (bd0[q] >= bd1[q]) { bd0[q] = dc; bi0[q] = jc; }
                            else                  { bd1[q] = dc; bi1[q] = jc; }
                            mymk[q] = fkey(fmaxf(bd0[q], bd1[q]));
                        }
                        bmaxKey[q] = __reduce_max_sync(FULLMASK, mymk[q]);
                        worstAdj[q] = unfkey(bmaxKey[q]) - s2i[q];
                    }
                }
            }
        }
    }

#pragma unroll
    for (int q = 0; q < 4; ++q) {
        const int row = row4 + q;
        IDX[row * KNB + lane] = bi0[q];
        WW[row * KNB + lane] = expf(-10.f * fmaxf(bd0[q], 0.f));
        if (lane < 8) {
            IDX[row * KNB + 32 + lane] = bi1[q];
            WW[row * KNB + 32 + lane] = expf(-10.f * fmaxf(bd1[q], 0.f));
        }
    }
}

// ---------------------------------------------------------------------------
// Aggregation: g_agg[i] = [mean_k(g_h[idx_k] * w_k), max_k(g_h[idx_k] * w_k)]
// ---------------------------------------------------------------------------
__global__ void __launch_bounds__(256) agg_k() {
    const float* __restrict__ H = g_h;
    const int* __restrict__ IDX = g_idx;
    const float* __restrict__ WW = g_w;
    float* __restrict__ AGG = g_agg;

    __shared__ int   sidx[4][KNB];
    __shared__ float sw[4][KNB];
    const int t = threadIdx.x;
    const int r = t >> 6;
    const int d = t & 63;
    const int row = blockIdx.x * 4 + r;

    if (d < KNB) {
        sidx[r][d] = IDX[row * KNB + d];
        sw[r][d] = WW[row * KNB + d];
    }
    __syncthreads();

    float sum = 0.f, mx = -3.4e38f;
#pragma unroll 4
    for (int k = 0; k < KNB; ++k) {
        int j = sidx[r][k];
        float v = H[j * PROP + d] * sw[r][k];
        sum += v;
        mx = fmaxf(mx, v);
    }
    AGG[row * HID + d]      = sum * (1.f / 40.f);
    AGG[row * HID + 64 + d] = mx;
}

// ---------------------------------------------------------------------------
// Host: full pipeline as a chain of kernel launches (graph-capturable).
// ---------------------------------------------------------------------------
extern "C" void kernel_launch(void* const* d_in, const int* in_sizes, int n_in,
                              void* d_out, int out_size) {
    const float* x_in  = (const float*)d_in[0];
    const float* fc1_W = (const float*)d_in[1];
    const float* fc1_b = (const float*)d_in[2];
    const float* fc2_W = (const float*)d_in[3];
    const float* fc2_b = (const float*)d_in[4];
    const float* gs_W  = (const float*)d_in[5];
    const float* gs_b  = (const float*)d_in[6];
    const float* gh_W  = (const float*)d_in[7];
    const float* gh_b  = (const float*)d_in[8];
    const float* go_W  = (const float*)d_in[9];
    const float* go_b  = (const float*)d_in[10];
    const float* d1_W  = (const float*)d_in[11];
    const float* d1_b  = (const float*)d_in[12];
    const float* d2_W  = (const float*)d_in[13];
    const float* d2_b  = (const float*)d_in[14];
    const float* d3_W  = (const float*)d_in[15];
    const float* d3_b  = (const float*)d_in[16];
    const float* fc3_W = (const float*)d_in[17];
    const float* fc3_b = (const float*)d_in[18];
    const float* fc4_W = (const float*)d_in[19];
    const float* fc4_b = (const float*)d_in[20];
    float* out = (float*)d_out;

    const int GB = NN / 32;   // 512 blocks (SIMT / knn)
    const int TB = NN / 64;   // 256 blocks (mma GEMMs)

    // fc1: x_in -> g_x(relu) [SIMT, KD=9]; fc2: g_x -> g_y(relu) [mma]
    gemm_k<9, 128, true><<<GB, 256>>>(x_in, -1, fc1_W, fc1_b, nullptr, 0);
    mmagemm_k<128, 128, true, false><<<TB, 128>>>(nullptr, 0, fc2_W, fc2_b, nullptr, 1);

    // x lives in g_y across layers; g_x is the ping-pong scratch.
    for (int i = 0; i < NLAYERS; ++i) {
        gemm4_k<false><<<GB, 128>>>(nullptr, 1, gs_W + i * HID * SPACE, gs_b + i * SPACE, nullptr, 4);
        mmagemm_k<128, 64, false, false><<<TB, 128>>>(nullptr, 1, gh_W + i * HID * PROP, gh_b + i * PROP, nullptr, 3);
        knn_k<<<GB, 256>>>();
        agg_k<<<NN / 4, 256>>>();
        // lin_out: [g_y | g_agg] @ go_W -> g_x (no relu)
        mmagemm_k<256, 128, false, true><<<TB, 128>>>(nullptr, 0, go_W + i * 2 * HID * HID, go_b + i * HID, nullptr, 0);
        mmagemm_k<128, 128, true, false><<<TB, 128>>>(nullptr, 0, d1_W + i * HID * HID, d1_b + i * HID, nullptr, 1);
        mmagemm_k<128, 128, true, false><<<TB, 128>>>(nullptr, 1, d2_W + i * HID * HID, d2_b + i * HID, nullptr, 0);
        mmagemm_k<128, 128, true, false><<<TB, 128>>>(nullptr, 0, d3_W + i * HID * HID, d3_b + i * HID, nullptr, 1);
    }

    // fc3: g_y -> g_x(relu) [mma]; fc4: g_x -> out [SIMT small]
    mmagemm_k<128, 128, true, false><<<TB, 128>>>(nullptr, 1, fc3_W, fc3_b, nullptr, 0);
    gemm4_k<false><<<GB, 128>>>(nullptr, 0, fc4_W, fc4_b, out, -1);
}